// round 16
// baseline (speedup 1.0000x reference)
#include <cuda_runtime.h>
#include <cuda_fp16.h>
#include <math.h>
#include <stdint.h>

// Problem constants
#define Bb  4
#define Ss  2048
#define Dd  1024
#define Hh  16
#define HDd 64
#define Mm  (Bb*Ss)          // 8192

// Scratch (no allocation allowed -> __device__ globals). All fp16.
__device__ __align__(16) __half g_q [Bb*Hh*Ss*HDd];  // [B,H,S,HD], pre-scaled by 0.125*log2(e)
__device__ __align__(16) __half g_k [Bb*Hh*Ss*HDd];  // [B,H,S,HD]
__device__ __align__(16) __half g_vT[Bb*Hh*HDd*Ss];  // [B,H,HD,S]  (transposed!)
__device__ __align__(16) __half g_o [Bb*Ss*Dd];      // [B,S,D]
__device__ __align__(16) __half g_xt[Mm*Dd];         // x -> fp16 [M,K]
__device__ __align__(16) __half g_wt[4][Dd*Dd];      // weights TRANSPOSED [N,K], fp16

__device__ __forceinline__ uint32_t pack_h2(float lo, float hi) {
    __half2 h = __float22half2_rn(make_float2(lo, hi));
    return *(uint32_t*)&h;
}

__device__ __forceinline__ float ex2(float x) {
    float r;
    asm("ex2.approx.f32 %0, %1;" : "=f"(r) : "f"(x));
    return r;
}

__device__ __forceinline__ void mma_f16(float c[4],
                                        uint32_t a0, uint32_t a1, uint32_t a2, uint32_t a3,
                                        uint32_t b0, uint32_t b1) {
    asm volatile(
        "mma.sync.aligned.m16n8k16.row.col.f32.f16.f16.f32 "
        "{%0,%1,%2,%3}, {%4,%5,%6,%7}, {%8,%9}, {%0,%1,%2,%3};"
        : "+f"(c[0]), "+f"(c[1]), "+f"(c[2]), "+f"(c[3])
        : "r"(a0), "r"(a1), "r"(a2), "r"(a3), "r"(b0), "r"(b1));
}

__device__ __forceinline__ void ldsm_x4(uint32_t& r0, uint32_t& r1,
                                        uint32_t& r2, uint32_t& r3, uint32_t addr) {
    asm volatile("ldmatrix.sync.aligned.m8n8.x4.shared.b16 {%0,%1,%2,%3}, [%4];"
                 : "=r"(r0), "=r"(r1), "=r"(r2), "=r"(r3) : "r"(addr));
}

__device__ __forceinline__ void cp16(void* dst_smem, const void* src) {
    uint32_t d = (uint32_t)__cvta_generic_to_shared(dst_smem);
    asm volatile("cp.async.cg.shared.global [%0], [%1], 16;\n" :: "r"(d), "l"(src));
}
#define CP_COMMIT() asm volatile("cp.async.commit_group;\n" ::: "memory")
#define CP_WAIT1()  asm volatile("cp.async.wait_group 1;\n" ::: "memory")
#define CP_WAIT0()  asm volatile("cp.async.wait_group 0;\n" ::: "memory")

// ---------------------------------------------------------------------------
// Pre-pass (merged): blocks 0..4095: x (fp32) -> g_xt (fp16), 8 elems/thread.
// blocks 4096..8191: transpose + convert one 32x32 weight tile.
// ---------------------------------------------------------------------------
__global__ __launch_bounds__(256)
void prepass(const float* __restrict__ x,
             const float* __restrict__ wq, const float* __restrict__ wk,
             const float* __restrict__ wv, const float* __restrict__ wo)
{
    const int bid = blockIdx.x;
    if (bid < 4096) {
        const size_t i = ((size_t)bid * 256 + threadIdx.x) * 8;
        float4 v0 = *(const float4*)(x + i);
        float4 v1 = *(const float4*)(x + i + 4);
        uint4 u;
        u.x = pack_h2(v0.x, v0.y);  u.y = pack_h2(v0.z, v0.w);
        u.z = pack_h2(v1.x, v1.y);  u.w = pack_h2(v1.z, v1.w);
        *(uint4*)(g_xt + i) = u;
    } else {
        __shared__ float sm[32][33];
        const int t2 = bid - 4096;
        const int w = t2 >> 10;              // 0..3
        const int tile = t2 & 1023;          // 0..1023
        const int k0 = (tile & 31) * 32;
        const int n0 = (tile >> 5) * 32;
        const float* src = (w == 0) ? wq : (w == 1) ? wk : (w == 2) ? wv : wo;
        __half* dst = g_wt[w];
        const int tx = threadIdx.x & 31, ty = threadIdx.x >> 5;
        #pragma unroll
        for (int i = 0; i < 4; i++)
            sm[ty + 8 * i][tx] = src[(size_t)(k0 + ty + 8 * i) * Dd + n0 + tx];
        __syncthreads();
        #pragma unroll
        for (int i = 0; i < 4; i++)
            dst[(size_t)(n0 + ty + 8 * i) * Dd + k0 + tx] = __float2half(sm[tx][ty + 8 * i]);
    }
}

// ---------------------------------------------------------------------------
// fp16 tensor-core GEMM (m16n8k16), 3-stage cp.async ring, k-tile 64.
// R16: block tile 64M x 128N (halved M) -> finer wave-quantization granule.
// 8 warps, warp tile 16m x 64n (1 m-atom x 8 n-atoms). Same per-element
// mma order as R14/R15 -> bit-identical output.
// ---------------------------------------------------------------------------
#define GP 36                      // words per smem row (k64 = 32 words + 4 pad)
#define GASTG_A (64*GP)            // words per A stage: 2304
#define GASTG_B (128*GP)           // words per B stage: 4608
#define GSTGW (GASTG_A+GASTG_B)    // words per stage: 6912 (27648 B)
#define GEMM_SMEM (3*GSTGW*4)      // 82944 bytes

#define QSCALE 0.18033688011112042f   // 0.125 * log2(e)

template<bool QKV>
__global__ __launch_bounds__(256, 2)
void tc_gemm(const float* __restrict__ bq, const float* __restrict__ bk,
             const float* __restrict__ bv, const float* __restrict__ bo,
             float* __restrict__ out_param)
{
    extern __shared__ uint32_t dsw[];

    int sel; const __half* A; const __half* W; const float* bias;
    int bnx;
    if (QKV) {
        sel = blockIdx.x >> 3;  bnx = blockIdx.x & 7;
        A = g_xt;  W = g_wt[sel];
        bias = (sel == 0) ? bq : (sel == 1) ? bk : bv;
    } else {
        sel = 3; bnx = blockIdx.x;
        A = g_o;  W = g_wt[3];  bias = bo;
    }

    const int t    = threadIdx.x;
    const int lane = t & 31;
    const int wid  = t >> 5;
    const int wm   = (wid & 3) * 16;     // 4 m-warps x 16
    const int wn   = (wid >> 2) * 64;    // 2 n-warps x 64
    const int g    = lane >> 2;
    const int tig  = lane & 3;

    const int bm = blockIdx.y * 64;
    const int bn = bnx * 128;

    const uint32_t sm0 = (uint32_t)__cvta_generic_to_shared(dsw);

    const int lrow = lane & 7;
    const int lmat = lane >> 3;
    const uint32_t lofsA = (uint32_t)((((lmat & 1) * 8 + lrow) * GP + (lmat >> 1) * 4) * 4);
    const uint32_t lofsB = (uint32_t)((((lmat >> 1) * 8 + lrow) * GP + (lmat & 1) * 4) * 4);

    // loaders: A 64 rows x 8 chunks (2/thread); B 128 rows x 8 chunks (4/thread)
    const int ra_r = t >> 2, ra_c = (t & 3) * 2;
    const int rb_r = t >> 1, rb_c = (t & 1) * 4;
    const __half* Arow = A + (size_t)(bm + ra_r) * Dd + ra_c * 8;
    const __half* Wrow = W + (size_t)(bn + rb_r) * Dd + rb_c * 8;

    const int NT = Dd / 64;   // 16 k-tiles

    auto issue = [&](int kt, int stg) {
        if (kt < NT) {
            const int k0 = kt * 64;
            uint32_t* Aw = dsw + stg * GSTGW;
            uint32_t* Bw = Aw + GASTG_A;
            #pragma unroll
            for (int j = 0; j < 2; j++)
                cp16(Aw + ra_r * GP + (ra_c + j) * 4, Arow + k0 + j * 8);
            #pragma unroll
            for (int j = 0; j < 4; j++)
                cp16(Bw + rb_r * GP + (rb_c + j) * 4, Wrow + k0 + j * 8);
        }
        CP_COMMIT();
    };

    float acc[8][4];
    #pragma unroll
    for (int na = 0; na < 8; na++)
        #pragma unroll
        for (int i = 0; i < 4; i++) acc[na][i] = 0.f;

    issue(0, 0);
    issue(1, 1);

    for (int kt = 0; kt < NT; kt++) {
        const int cur = kt % 3;
        CP_WAIT1();
        __syncthreads();
        issue(kt + 2, (kt + 2) % 3);

        const uint32_t Abase = sm0 + (uint32_t)(cur * GSTGW) * 4;
        const uint32_t Bbase = Abase + (uint32_t)GASTG_A * 4;

        #pragma unroll
        for (int ks = 0; ks < 4; ks++) {
            const uint32_t kwo = (uint32_t)(ks * 8 * 4);
            uint32_t a0, a1, a2, a3;
            ldsm_x4(a0, a1, a2, a3, Abase + (uint32_t)(wm * GP) * 4 + kwo + lofsA);
            #pragma unroll
            for (int p = 0; p < 4; p++) {
                uint32_t b00, b01, b10, b11;
                const uint32_t rb = Bbase + (uint32_t)((wn + p * 16) * GP) * 4 + kwo + lofsB;
                ldsm_x4(b00, b01, b10, b11, rb);
                mma_f16(acc[2*p    ], a0, a1, a2, a3, b00, b01);
                mma_f16(acc[2*p + 1], a0, a1, a2, a3, b10, b11);
            }
        }
    }

    // ---- epilogue ----
    #pragma unroll
    for (int na = 0; na < 8; na++) {
        const int row0 = bm + wm + g;
        const int col  = bn + wn + na * 8 + tig * 2;
        const float bia0 = bias[col], bia1 = bias[col + 1];
        #pragma unroll
        for (int half_i = 0; half_i < 2; half_i++) {
            const int mrow = row0 + half_i * 8;
            float v0 = acc[na][half_i * 2 + 0] + bia0;
            float v1 = acc[na][half_i * 2 + 1] + bia1;
            if (QKV) {
                const int b = mrow / Ss, s = mrow % Ss;
                const int h = col / HDd, d = col % HDd;
                if (sel == 0) { v0 *= QSCALE; v1 *= QSCALE; }
                if (sel == 2) {
                    __half* dst = g_vT + (((size_t)b * Hh + h) * HDd) * Ss + s;
                    dst[(size_t)d * Ss]       = __float2half(v0);
                    dst[(size_t)(d + 1) * Ss] = __float2half(v1);
                } else {
                    __half* dst = (sel == 0) ? g_q : g_k;
                    *(uint32_t*)&dst[(((size_t)b * Hh + h) * Ss + s) * HDd + d] =
                        pack_h2(v0, v1);
                }
            } else {
                *(float2*)&out_param[(size_t)mrow * Dd + col] = make_float2(v0, v1);
            }
        }
    }
}

// ---------------------------------------------------------------------------
// fp16 tensor-core flash attention (causal), m16n8k16, FA2-style.
// [frozen from R15 — at mma.sync HMMA ceiling]
// ---------------------------------------------------------------------------
#define FP 36                         // words per smem row
#define TSZ (64*FP)                   // words per tile (2304)
#define FA_SMEM (4*TSZ*4)             // K x2 + V x2 = 36864 bytes

__global__ __launch_bounds__(128)
void flash_attn_tc()
{
    extern __shared__ uint32_t dsw[];

    const int tid  = threadIdx.x;
    const int lane = tid & 31;
    const int wid  = tid >> 5;
    const int g    = lane >> 2;
    const int tig  = lane & 3;
    const int q0   = (int)(gridDim.x - 1 - blockIdx.x) * 64;   // heavy-first
    const int bh   = blockIdx.y;
    const int qr0  = q0 + wid * 16;

    const __half* qb  = g_q  + (size_t)bh * Ss * HDd;
    const __half* kb  = g_k  + (size_t)bh * Ss * HDd;
    const __half* vtb = g_vT + (size_t)bh * HDd * Ss;

    const uint32_t sm0 = (uint32_t)__cvta_generic_to_shared(dsw);

    const int lrow = lane & 7;
    const int lmat = lane >> 3;
    const uint32_t lofs = (uint32_t)((((lmat >> 1) * 8 + lrow) * FP + (lmat & 1) * 4) * 4);

    uint32_t qf[4][4];
    #pragma unroll
    for (int c = 0; c < 4; c++) {
        qf[c][0] = *(const uint32_t*)&qb[(size_t)(qr0 + g    ) * HDd + c * 16 + tig * 2    ];
        qf[c][1] = *(const uint32_t*)&qb[(size_t)(qr0 + g + 8) * HDd + c * 16 + tig * 2    ];
        qf[c][2] = *(const uint32_t*)&qb[(size_t)(qr0 + g    ) * HDd + c * 16 + tig * 2 + 8];
        qf[c][3] = *(const uint32_t*)&qb[(size_t)(qr0 + g + 8) * HDd + c * 16 + tig * 2 + 8];
    }

    float acc[8][4];
    #pragma unroll
    for (int na = 0; na < 8; na++)
        #pragma unroll
        for (int i = 0; i < 4; i++) acc[na][i] = 0.f;

    float m_lo = -INFINITY, m_hi = -INFINITY;
    float l_lo = 0.f, l_hi = 0.f;

    const int nt = q0 / 64 + 1;

    auto issue_tile = [&](int kt, int buf) {
        uint32_t* Kd = dsw + buf * TSZ;
        uint32_t* Vd = dsw + (2 + buf) * TSZ;
        #pragma unroll
        for (int i = 0; i < 4; i++) {
            const int idx = tid + i * 128;
            const int row = idx >> 3;
            const int c   = idx & 7;
            cp16(Kd + row * FP + c * 4, kb  + (size_t)(kt * 64 + row) * HDd + c * 8);
            cp16(Vd + row * FP + c * 4, vtb + (size_t)row * Ss + kt * 64 + c * 8);
        }
        CP_COMMIT();
    };

    issue_tile(0, 0);

    for (int kt = 0; kt < nt; kt++) {
        const int cur = kt & 1;
        CP_WAIT0();
        __syncthreads();
        if (kt + 1 < nt) issue_tile(kt + 1, cur ^ 1);

        const uint32_t Kc = sm0 + (uint32_t)(cur * TSZ) * 4 + lofs;
        const uint32_t Vc = sm0 + (uint32_t)((2 + cur) * TSZ) * 4 + lofs;

        float s[8][4];
        #pragma unroll
        for (int na = 0; na < 8; na++)
            #pragma unroll
            for (int i = 0; i < 4; i++) s[na][i] = 0.f;

        #pragma unroll
        for (int c = 0; c < 4; c++) {
            #pragma unroll
            for (int p = 0; p < 4; p++) {
                uint32_t b00, b01, b10, b11;
                ldsm_x4(b00, b01, b10, b11, Kc + (uint32_t)((p * 16 * FP + c * 8) * 4));
                mma_f16(s[2*p    ], qf[c][0], qf[c][1], qf[c][2], qf[c][3], b00, b01);
                mma_f16(s[2*p + 1], qf[c][0], qf[c][1], qf[c][2], qf[c][3], b10, b11);
            }
        }

        if (kt == nt - 1) {
            const int rlo = qr0 + g, rhi = qr0 + g + 8;
            #pragma unroll
            for (int na = 0; na < 8; na++) {
                const int c0 = kt * 64 + na * 8 + tig * 2;
                const int c1 = c0 + 1;
                if (c0 > rlo) s[na][0] = -INFINITY;
                if (c1 > rlo) s[na][1] = -INFINITY;
                if (c0 > rhi) s[na][2] = -INFINITY;
                if (c1 > rhi) s[na][3] = -INFINITY;
            }
        }

        float tm_lo = -INFINITY, tm_hi = -INFINITY;
        #pragma unroll
        for (int na = 0; na < 8; na++) {
            tm_lo = fmaxf(tm_lo, fmaxf(s[na][0], s[na][1]));
            tm_hi = fmaxf(tm_hi, fmaxf(s[na][2], s[na][3]));
        }
        tm_lo = fmaxf(tm_lo, __shfl_xor_sync(0xffffffffu, tm_lo, 1));
        tm_lo = fmaxf(tm_lo, __shfl_xor_sync(0xffffffffu, tm_lo, 2));
        tm_hi = fmaxf(tm_hi, __shfl_xor_sync(0xffffffffu, tm_hi, 1));
        tm_hi = fmaxf(tm_hi, __shfl_xor_sync(0xffffffffu, tm_hi, 2));

        const float mn_lo = fmaxf(m_lo, tm_lo);
        const float mn_hi = fmaxf(m_hi, tm_hi);
        const float sc_lo = ex2(m_lo - mn_lo);
        const float sc_hi = ex2(m_hi - mn_hi);
        m_lo = mn_lo;  m_hi = mn_hi;

        float sum_lo = 0.f, sum_hi = 0.f;
        #pragma unroll
        for (int na = 0; na < 8; na++) {
            s[na][0] = ex2(s[na][0] - mn_lo);
            s[na][1] = ex2(s[na][1] - mn_lo);
            s[na][2] = ex2(s[na][2] - mn_hi);
            s[na][3] = ex2(s[na][3] - mn_hi);
            sum_lo += s[na][0] + s[na][1];
            sum_hi += s[na][2] + s[na][3];
        }
        l_lo = l_lo * sc_lo + sum_lo;
        l_hi = l_hi * sc_hi + sum_hi;

        #pragma unroll
        for (int na = 0; na < 8; na++) {
            acc[na][0] *= sc_lo; acc[na][1] *= sc_lo;
            acc[na][2] *= sc_hi; acc[na][3] *= sc_hi;
        }

        #pragma unroll
        for (int c = 0; c < 4; c++) {
            const uint32_t a0 = pack_h2(s[2 * c    ][0], s[2 * c    ][1]);
            const uint32_t a1 = pack_h2(s[2 * c    ][2], s[2 * c    ][3]);
            const uint32_t a2 = pack_h2(s[2 * c + 1][0], s[2 * c + 1][1]);
            const uint32_t a3 = pack_h2(s[2 * c + 1][2], s[2 * c + 1][3]);
            #pragma unroll
            for (int p = 0; p < 4; p++) {
                uint32_t b00, b01, b10, b11;
                ldsm_x4(b00, b01, b10, b11, Vc + (uint32_t)((p * 16 * FP + c * 8) * 4));
                mma_f16(acc[2*p    ], a0, a1, a2, a3, b00, b01);
                mma_f16(acc[2*p + 1], a0, a1, a2, a3, b10, b11);
            }
        }
    }

    l_lo += __shfl_xor_sync(0xffffffffu, l_lo, 1);
    l_lo += __shfl_xor_sync(0xffffffffu, l_lo, 2);
    l_hi += __shfl_xor_sync(0xffffffffu, l_hi, 1);
    l_hi += __shfl_xor_sync(0xffffffffu, l_hi, 2);

    const float inv_lo = 1.f / l_lo;
    const float inv_hi = 1.f / l_hi;
    const int b = bh / Hh, h = bh % Hh;
    __half* olo = g_o + ((size_t)b * Ss + (qr0 + g    )) * Dd + h * HDd;
    __half* ohi = g_o + ((size_t)b * Ss + (qr0 + g + 8)) * Dd + h * HDd;
    #pragma unroll
    for (int na = 0; na < 8; na++) {
        *(uint32_t*)&olo[na * 8 + tig * 2] = pack_h2(acc[na][0] * inv_lo, acc[na][1] * inv_lo);
        *(uint32_t*)&ohi[na * 8 + tig * 2] = pack_h2(acc[na][2] * inv_hi, acc[na][3] * inv_hi);
    }
}

// ---------------------------------------------------------------------------
extern "C" void kernel_launch(void* const* d_in, const int* in_sizes, int n_in,
                              void* d_out, int out_size)
{
    const float* x  = (const float*)d_in[0];
    const float* wq = (const float*)d_in[1];
    const float* bq = (const float*)d_in[2];
    const float* wk = (const float*)d_in[3];
    const float* bk = (const float*)d_in[4];
    const float* wv = (const float*)d_in[5];
    const float* bv = (const float*)d_in[6];
    const float* wo = (const float*)d_in[7];
    const float* bo = (const float*)d_in[8];
    float* out = (float*)d_out;

    cudaFuncSetAttribute(tc_gemm<true>,  cudaFuncAttributeMaxDynamicSharedMemorySize, GEMM_SMEM);
    cudaFuncSetAttribute(tc_gemm<false>, cudaFuncAttributeMaxDynamicSharedMemorySize, GEMM_SMEM);
    cudaFuncSetAttribute(flash_attn_tc,  cudaFuncAttributeMaxDynamicSharedMemorySize, FA_SMEM);

    // merged pre-pass: x -> fp16 (blocks 0..4095); weights transpose (4096..8191)
    prepass<<<8192, 256>>>(x, wq, wk, wv, wo);

    // fused QKV projection: 64M x 128N tiles
    dim3 qgrid(24, Mm / 64);              // (24, 128)
    tc_gemm<true><<<qgrid, 256, GEMM_SMEM>>>(bq, bk, bv, nullptr, nullptr);

    // attention (heavy-first)
    dim3 agrid(Ss / 64, Bb * Hh);         // (32, 64)
    flash_attn_tc<<<agrid, 128, FA_SMEM>>>();

    // output projection: 64M x 128N tiles
    dim3 ogrid(8, Mm / 64);               // (8, 128)
    tc_gemm<false><<<ogrid, 256, GEMM_SMEM>>>(nullptr, nullptr, nullptr, bo, out);
}

// round 17
// speedup vs baseline: 1.1120x; 1.1120x over previous
#include <cuda_runtime.h>
#include <cuda_fp16.h>
#include <math.h>
#include <stdint.h>

// Problem constants
#define Bb  4
#define Ss  2048
#define Dd  1024
#define Hh  16
#define HDd 64
#define Mm  (Bb*Ss)          // 8192

// Scratch (no allocation allowed -> __device__ globals). All fp16.
__device__ __align__(16) __half g_q [Bb*Hh*Ss*HDd];  // [B,H,S,HD], pre-scaled by 0.125*log2(e)
__device__ __align__(16) __half g_k [Bb*Hh*Ss*HDd];  // [B,H,S,HD]
__device__ __align__(16) __half g_vT[Bb*Hh*HDd*Ss];  // [B,H,HD,S]  (transposed!)
__device__ __align__(16) __half g_o [Bb*Ss*Dd];      // [B,S,D]
__device__ __align__(16) __half g_xt[Mm*Dd];         // x -> fp16 [M,K]
__device__ __align__(16) __half g_wt[4][Dd*Dd];      // weights TRANSPOSED [N,K], fp16

__device__ __forceinline__ uint32_t pack_h2(float lo, float hi) {
    __half2 h = __float22half2_rn(make_float2(lo, hi));
    return *(uint32_t*)&h;
}

__device__ __forceinline__ float ex2(float x) {
    float r;
    asm("ex2.approx.f32 %0, %1;" : "=f"(r) : "f"(x));
    return r;
}

__device__ __forceinline__ void mma_f16(float c[4],
                                        uint32_t a0, uint32_t a1, uint32_t a2, uint32_t a3,
                                        uint32_t b0, uint32_t b1) {
    asm volatile(
        "mma.sync.aligned.m16n8k16.row.col.f32.f16.f16.f32 "
        "{%0,%1,%2,%3}, {%4,%5,%6,%7}, {%8,%9}, {%0,%1,%2,%3};"
        : "+f"(c[0]), "+f"(c[1]), "+f"(c[2]), "+f"(c[3])
        : "r"(a0), "r"(a1), "r"(a2), "r"(a3), "r"(b0), "r"(b1));
}

__device__ __forceinline__ void ldsm_x4(uint32_t& r0, uint32_t& r1,
                                        uint32_t& r2, uint32_t& r3, uint32_t addr) {
    asm volatile("ldmatrix.sync.aligned.m8n8.x4.shared.b16 {%0,%1,%2,%3}, [%4];"
                 : "=r"(r0), "=r"(r1), "=r"(r2), "=r"(r3) : "r"(addr));
}

__device__ __forceinline__ void cp16(void* dst_smem, const void* src) {
    uint32_t d = (uint32_t)__cvta_generic_to_shared(dst_smem);
    asm volatile("cp.async.cg.shared.global [%0], [%1], 16;\n" :: "r"(d), "l"(src));
}
#define CP_COMMIT() asm volatile("cp.async.commit_group;\n" ::: "memory")
#define CP_WAIT1()  asm volatile("cp.async.wait_group 1;\n" ::: "memory")
#define CP_WAIT0()  asm volatile("cp.async.wait_group 0;\n" ::: "memory")

// ---------------------------------------------------------------------------
// Pre-pass (merged): blocks 0..4095: x (fp32) -> g_xt (fp16), 8 elems/thread.
// blocks 4096..8191: transpose + convert one 32x32 weight tile.
// ---------------------------------------------------------------------------
__global__ __launch_bounds__(256)
void prepass(const float* __restrict__ x,
             const float* __restrict__ wq, const float* __restrict__ wk,
             const float* __restrict__ wv, const float* __restrict__ wo)
{
    const int bid = blockIdx.x;
    if (bid < 4096) {
        const size_t i = ((size_t)bid * 256 + threadIdx.x) * 8;
        float4 v0 = *(const float4*)(x + i);
        float4 v1 = *(const float4*)(x + i + 4);
        uint4 u;
        u.x = pack_h2(v0.x, v0.y);  u.y = pack_h2(v0.z, v0.w);
        u.z = pack_h2(v1.x, v1.y);  u.w = pack_h2(v1.z, v1.w);
        *(uint4*)(g_xt + i) = u;
    } else {
        __shared__ float sm[32][33];
        const int t2 = bid - 4096;
        const int w = t2 >> 10;              // 0..3
        const int tile = t2 & 1023;          // 0..1023
        const int k0 = (tile & 31) * 32;
        const int n0 = (tile >> 5) * 32;
        const float* src = (w == 0) ? wq : (w == 1) ? wk : (w == 2) ? wv : wo;
        __half* dst = g_wt[w];
        const int tx = threadIdx.x & 31, ty = threadIdx.x >> 5;
        #pragma unroll
        for (int i = 0; i < 4; i++)
            sm[ty + 8 * i][tx] = src[(size_t)(k0 + ty + 8 * i) * Dd + n0 + tx];
        __syncthreads();
        #pragma unroll
        for (int i = 0; i < 4; i++)
            dst[(size_t)(n0 + ty + 8 * i) * Dd + k0 + tx] = __float2half(sm[tx][ty + 8 * i]);
    }
}

// ---------------------------------------------------------------------------
// fp16 tensor-core GEMM (m16n8k16), 3-stage cp.async ring, k-tile 64.
// Block tile 128M x 128N, 8 warps (warp 32m x 64n) — R14/R15 shape.
// R17: O path (QKV=false) runs TWO m-halves per block (M-tile 256) ->
// grid 128 blocks = single wave, zero tail. Same per-element math order ->
// bit-identical output.
// ---------------------------------------------------------------------------
#define GP 36                      // words per smem row (k64 = 32 words + 4 pad)
#define GASTG (128*GP)             // words per A (or B) stage: 4608
#define GSTGW (2*GASTG)            // words per stage A+B: 9216 (36864 B)
#define GEMM_SMEM (3*GSTGW*4)      // 110592 bytes

#define QSCALE 0.18033688011112042f   // 0.125 * log2(e)

template<bool QKV>
__global__ __launch_bounds__(256, 2)
void tc_gemm(const float* __restrict__ bq, const float* __restrict__ bk,
             const float* __restrict__ bv, const float* __restrict__ bo,
             float* __restrict__ out_param)
{
    extern __shared__ uint32_t dsw[];

    int sel; const __half* A; const __half* W; const float* bias;
    int bnx;
    if (QKV) {
        sel = blockIdx.x >> 3;  bnx = blockIdx.x & 7;
        A = g_xt;  W = g_wt[sel];
        bias = (sel == 0) ? bq : (sel == 1) ? bk : bv;
    } else {
        sel = 3; bnx = blockIdx.x;
        A = g_o;  W = g_wt[3];  bias = bo;
    }

    const int t    = threadIdx.x;
    const int lane = t & 31;
    const int wid  = t >> 5;
    const int wm   = (wid & 3) * 32;
    const int wn   = (wid >> 2) * 64;
    const int g    = lane >> 2;
    const int tig  = lane & 3;

    const int bn = bnx * 128;

    const uint32_t sm0 = (uint32_t)__cvta_generic_to_shared(dsw);

    const int lrow = lane & 7;
    const int lmat = lane >> 3;
    const uint32_t lofsA = (uint32_t)((((lmat & 1) * 8 + lrow) * GP + (lmat >> 1) * 4) * 4);
    const uint32_t lofsB = (uint32_t)((((lmat >> 1) * 8 + lrow) * GP + (lmat & 1) * 4) * 4);

    const int lr = t >> 1;
    const int lcp = t & 1;
    const __half* Wrow = W + (size_t)(bn + lr) * Dd + lcp * 32;

    const int NT = Dd / 64;   // 16 k-tiles
    const int NH = QKV ? 1 : 2;   // m-halves per block

    for (int mh = 0; mh < NH; mh++) {
        const int bm = QKV ? (int)blockIdx.y * 128 : (int)blockIdx.y * 256 + mh * 128;
        const __half* Arow = A + (size_t)(bm + lr) * Dd + lcp * 32;

        auto issue = [&](int kt, int stg) {
            if (kt < NT) {
                const int k0 = kt * 64;
                uint32_t* Aw = dsw + stg * GSTGW;
                uint32_t* Bw = Aw + GASTG;
                #pragma unroll
                for (int j = 0; j < 4; j++) {
                    cp16(Aw + lr * GP + (lcp * 4 + j) * 4, Arow + k0 + j * 8);
                    cp16(Bw + lr * GP + (lcp * 4 + j) * 4, Wrow + k0 + j * 8);
                }
            }
            CP_COMMIT();
        };

        float acc[2][8][4];
        #pragma unroll
        for (int ma = 0; ma < 2; ma++)
            #pragma unroll
            for (int na = 0; na < 8; na++)
                #pragma unroll
                for (int i = 0; i < 4; i++) acc[ma][na][i] = 0.f;

        issue(0, 0);
        issue(1, 1);

        for (int kt = 0; kt < NT; kt++) {
            const int cur = kt % 3;
            CP_WAIT1();
            __syncthreads();
            issue(kt + 2, (kt + 2) % 3);

            const uint32_t Abase = sm0 + (uint32_t)(cur * GSTGW) * 4;
            const uint32_t Bbase = Abase + (uint32_t)GASTG * 4;

            #pragma unroll
            for (int ks = 0; ks < 4; ks++) {
                const uint32_t kwo = (uint32_t)(ks * 8 * 4);
                uint32_t a[2][4];
                #pragma unroll
                for (int ma = 0; ma < 2; ma++) {
                    const uint32_t ra = Abase + (uint32_t)((wm + ma * 16) * GP) * 4 + kwo + lofsA;
                    ldsm_x4(a[ma][0], a[ma][1], a[ma][2], a[ma][3], ra);
                }
                #pragma unroll
                for (int p = 0; p < 4; p++) {
                    uint32_t b00, b01, b10, b11;
                    const uint32_t rb = Bbase + (uint32_t)((wn + p * 16) * GP) * 4 + kwo + lofsB;
                    ldsm_x4(b00, b01, b10, b11, rb);
                    #pragma unroll
                    for (int ma = 0; ma < 2; ma++) {
                        mma_f16(acc[ma][2*p    ], a[ma][0], a[ma][1], a[ma][2], a[ma][3], b00, b01);
                        mma_f16(acc[ma][2*p + 1], a[ma][0], a[ma][1], a[ma][2], a[ma][3], b10, b11);
                    }
                }
            }
        }

        // ---- epilogue ----
        #pragma unroll
        for (int ma = 0; ma < 2; ma++) {
            #pragma unroll
            for (int na = 0; na < 8; na++) {
                const int row0 = bm + wm + ma * 16 + g;
                const int col  = bn + wn + na * 8 + tig * 2;
                const float bia0 = bias[col], bia1 = bias[col + 1];
                #pragma unroll
                for (int half_i = 0; half_i < 2; half_i++) {
                    const int mrow = row0 + half_i * 8;
                    float v0 = acc[ma][na][half_i * 2 + 0] + bia0;
                    float v1 = acc[ma][na][half_i * 2 + 1] + bia1;
                    if (QKV) {
                        const int b = mrow / Ss, s = mrow % Ss;
                        const int h = col / HDd, d = col % HDd;
                        if (sel == 0) { v0 *= QSCALE; v1 *= QSCALE; }
                        if (sel == 2) {
                            __half* dst = g_vT + (((size_t)b * Hh + h) * HDd) * Ss + s;
                            dst[(size_t)d * Ss]       = __float2half(v0);
                            dst[(size_t)(d + 1) * Ss] = __float2half(v1);
                        } else {
                            __half* dst = (sel == 0) ? g_q : g_k;
                            *(uint32_t*)&dst[(((size_t)b * Hh + h) * Ss + s) * HDd + d] =
                                pack_h2(v0, v1);
                        }
                    } else {
                        *(float2*)&out_param[(size_t)mrow * Dd + col] = make_float2(v0, v1);
                    }
                }
            }
        }

        if (NH == 2) __syncthreads();   // half 2's cp.async reuses stage 0
    }
}

// ---------------------------------------------------------------------------
// fp16 tensor-core flash attention (causal), m16n8k16, FA2-style.
// [frozen from R15 — at mma.sync HMMA ceiling; heavy-first ordering]
// ---------------------------------------------------------------------------
#define FP 36                         // words per smem row
#define TSZ (64*FP)                   // words per tile (2304)
#define FA_SMEM (4*TSZ*4)             // K x2 + V x2 = 36864 bytes

__global__ __launch_bounds__(128)
void flash_attn_tc()
{
    extern __shared__ uint32_t dsw[];

    const int tid  = threadIdx.x;
    const int lane = tid & 31;
    const int wid  = tid >> 5;
    const int g    = lane >> 2;
    const int tig  = lane & 3;
    const int q0   = (int)(gridDim.x - 1 - blockIdx.x) * 64;   // heavy-first
    const int bh   = blockIdx.y;
    const int qr0  = q0 + wid * 16;

    const __half* qb  = g_q  + (size_t)bh * Ss * HDd;
    const __half* kb  = g_k  + (size_t)bh * Ss * HDd;
    const __half* vtb = g_vT + (size_t)bh * HDd * Ss;

    const uint32_t sm0 = (uint32_t)__cvta_generic_to_shared(dsw);

    const int lrow = lane & 7;
    const int lmat = lane >> 3;
    const uint32_t lofs = (uint32_t)((((lmat >> 1) * 8 + lrow) * FP + (lmat & 1) * 4) * 4);

    uint32_t qf[4][4];
    #pragma unroll
    for (int c = 0; c < 4; c++) {
        qf[c][0] = *(const uint32_t*)&qb[(size_t)(qr0 + g    ) * HDd + c * 16 + tig * 2    ];
        qf[c][1] = *(const uint32_t*)&qb[(size_t)(qr0 + g + 8) * HDd + c * 16 + tig * 2    ];
        qf[c][2] = *(const uint32_t*)&qb[(size_t)(qr0 + g    ) * HDd + c * 16 + tig * 2 + 8];
        qf[c][3] = *(const uint32_t*)&qb[(size_t)(qr0 + g + 8) * HDd + c * 16 + tig * 2 + 8];
    }

    float acc[8][4];
    #pragma unroll
    for (int na = 0; na < 8; na++)
        #pragma unroll
        for (int i = 0; i < 4; i++) acc[na][i] = 0.f;

    float m_lo = -INFINITY, m_hi = -INFINITY;
    float l_lo = 0.f, l_hi = 0.f;

    const int nt = q0 / 64 + 1;

    auto issue_tile = [&](int kt, int buf) {
        uint32_t* Kd = dsw + buf * TSZ;
        uint32_t* Vd = dsw + (2 + buf) * TSZ;
        #pragma unroll
        for (int i = 0; i < 4; i++) {
            const int idx = tid + i * 128;
            const int row = idx >> 3;
            const int c   = idx & 7;
            cp16(Kd + row * FP + c * 4, kb  + (size_t)(kt * 64 + row) * HDd + c * 8);
            cp16(Vd + row * FP + c * 4, vtb + (size_t)row * Ss + kt * 64 + c * 8);
        }
        CP_COMMIT();
    };

    issue_tile(0, 0);

    for (int kt = 0; kt < nt; kt++) {
        const int cur = kt & 1;
        CP_WAIT0();
        __syncthreads();
        if (kt + 1 < nt) issue_tile(kt + 1, cur ^ 1);

        const uint32_t Kc = sm0 + (uint32_t)(cur * TSZ) * 4 + lofs;
        const uint32_t Vc = sm0 + (uint32_t)((2 + cur) * TSZ) * 4 + lofs;

        float s[8][4];
        #pragma unroll
        for (int na = 0; na < 8; na++)
            #pragma unroll
            for (int i = 0; i < 4; i++) s[na][i] = 0.f;

        #pragma unroll
        for (int c = 0; c < 4; c++) {
            #pragma unroll
            for (int p = 0; p < 4; p++) {
                uint32_t b00, b01, b10, b11;
                ldsm_x4(b00, b01, b10, b11, Kc + (uint32_t)((p * 16 * FP + c * 8) * 4));
                mma_f16(s[2*p    ], qf[c][0], qf[c][1], qf[c][2], qf[c][3], b00, b01);
                mma_f16(s[2*p + 1], qf[c][0], qf[c][1], qf[c][2], qf[c][3], b10, b11);
            }
        }

        if (kt == nt - 1) {
            const int rlo = qr0 + g, rhi = qr0 + g + 8;
            #pragma unroll
            for (int na = 0; na < 8; na++) {
                const int c0 = kt * 64 + na * 8 + tig * 2;
                const int c1 = c0 + 1;
                if (c0 > rlo) s[na][0] = -INFINITY;
                if (c1 > rlo) s[na][1] = -INFINITY;
                if (c0 > rhi) s[na][2] = -INFINITY;
                if (c1 > rhi) s[na][3] = -INFINITY;
            }
        }

        float tm_lo = -INFINITY, tm_hi = -INFINITY;
        #pragma unroll
        for (int na = 0; na < 8; na++) {
            tm_lo = fmaxf(tm_lo, fmaxf(s[na][0], s[na][1]));
            tm_hi = fmaxf(tm_hi, fmaxf(s[na][2], s[na][3]));
        }
        tm_lo = fmaxf(tm_lo, __shfl_xor_sync(0xffffffffu, tm_lo, 1));
        tm_lo = fmaxf(tm_lo, __shfl_xor_sync(0xffffffffu, tm_lo, 2));
        tm_hi = fmaxf(tm_hi, __shfl_xor_sync(0xffffffffu, tm_hi, 1));
        tm_hi = fmaxf(tm_hi, __shfl_xor_sync(0xffffffffu, tm_hi, 2));

        const float mn_lo = fmaxf(m_lo, tm_lo);
        const float mn_hi = fmaxf(m_hi, tm_hi);
        const float sc_lo = ex2(m_lo - mn_lo);
        const float sc_hi = ex2(m_hi - mn_hi);
        m_lo = mn_lo;  m_hi = mn_hi;

        float sum_lo = 0.f, sum_hi = 0.f;
        #pragma unroll
        for (int na = 0; na < 8; na++) {
            s[na][0] = ex2(s[na][0] - mn_lo);
            s[na][1] = ex2(s[na][1] - mn_lo);
            s[na][2] = ex2(s[na][2] - mn_hi);
            s[na][3] = ex2(s[na][3] - mn_hi);
            sum_lo += s[na][0] + s[na][1];
            sum_hi += s[na][2] + s[na][3];
        }
        l_lo = l_lo * sc_lo + sum_lo;
        l_hi = l_hi * sc_hi + sum_hi;

        #pragma unroll
        for (int na = 0; na < 8; na++) {
            acc[na][0] *= sc_lo; acc[na][1] *= sc_lo;
            acc[na][2] *= sc_hi; acc[na][3] *= sc_hi;
        }

        #pragma unroll
        for (int c = 0; c < 4; c++) {
            const uint32_t a0 = pack_h2(s[2 * c    ][0], s[2 * c    ][1]);
            const uint32_t a1 = pack_h2(s[2 * c    ][2], s[2 * c    ][3]);
            const uint32_t a2 = pack_h2(s[2 * c + 1][0], s[2 * c + 1][1]);
            const uint32_t a3 = pack_h2(s[2 * c + 1][2], s[2 * c + 1][3]);
            #pragma unroll
            for (int p = 0; p < 4; p++) {
                uint32_t b00, b01, b10, b11;
                ldsm_x4(b00, b01, b10, b11, Vc + (uint32_t)((p * 16 * FP + c * 8) * 4));
                mma_f16(acc[2*p    ], a0, a1, a2, a3, b00, b01);
                mma_f16(acc[2*p + 1], a0, a1, a2, a3, b10, b11);
            }
        }
    }

    l_lo += __shfl_xor_sync(0xffffffffu, l_lo, 1);
    l_lo += __shfl_xor_sync(0xffffffffu, l_lo, 2);
    l_hi += __shfl_xor_sync(0xffffffffu, l_hi, 1);
    l_hi += __shfl_xor_sync(0xffffffffu, l_hi, 2);

    const float inv_lo = 1.f / l_lo;
    const float inv_hi = 1.f / l_hi;
    const int b = bh / Hh, h = bh % Hh;
    __half* olo = g_o + ((size_t)b * Ss + (qr0 + g    )) * Dd + h * HDd;
    __half* ohi = g_o + ((size_t)b * Ss + (qr0 + g + 8)) * Dd + h * HDd;
    #pragma unroll
    for (int na = 0; na < 8; na++) {
        *(uint32_t*)&olo[na * 8 + tig * 2] = pack_h2(acc[na][0] * inv_lo, acc[na][1] * inv_lo);
        *(uint32_t*)&ohi[na * 8 + tig * 2] = pack_h2(acc[na][2] * inv_hi, acc[na][3] * inv_hi);
    }
}

// ---------------------------------------------------------------------------
extern "C" void kernel_launch(void* const* d_in, const int* in_sizes, int n_in,
                              void* d_out, int out_size)
{
    const float* x  = (const float*)d_in[0];
    const float* wq = (const float*)d_in[1];
    const float* bq = (const float*)d_in[2];
    const float* wk = (const float*)d_in[3];
    const float* bk = (const float*)d_in[4];
    const float* wv = (const float*)d_in[5];
    const float* bv = (const float*)d_in[6];
    const float* wo = (const float*)d_in[7];
    const float* bo = (const float*)d_in[8];
    float* out = (float*)d_out;

    cudaFuncSetAttribute(tc_gemm<true>,  cudaFuncAttributeMaxDynamicSharedMemorySize, GEMM_SMEM);
    cudaFuncSetAttribute(tc_gemm<false>, cudaFuncAttributeMaxDynamicSharedMemorySize, GEMM_SMEM);
    cudaFuncSetAttribute(flash_attn_tc,  cudaFuncAttributeMaxDynamicSharedMemorySize, FA_SMEM);

    // merged pre-pass: x -> fp16 (blocks 0..4095); weights transpose (4096..8191)
    prepass<<<8192, 256>>>(x, wq, wk, wv, wo);

    // fused QKV projection: 128M x 128N tiles (R15 shape)
    dim3 qgrid(24, Mm / 128);             // (24, 64)
    tc_gemm<true><<<qgrid, 256, GEMM_SMEM>>>(bq, bk, bv, nullptr, nullptr);

    // attention (heavy-first)
    dim3 agrid(Ss / 64, Bb * Hh);         // (32, 64)
    flash_attn_tc<<<agrid, 128, FA_SMEM>>>();

    // output projection: 256M x 128N per block -> 128 blocks, single wave
    dim3 ogrid(8, Mm / 256);              // (8, 32)
    tc_gemm<false><<<ogrid, 256, GEMM_SMEM>>>(nullptr, nullptr, nullptr, bo, out);
}